// round 1
// baseline (speedup 1.0000x reference)
#include <cuda_runtime.h>
#include <cuda_bf16.h>

// Problem constants (from reference): N=50000, E=800000, H=64, L=4
#define MAXN 50000
#define MAXE 800000
#define HDIM 64

// Scratch: __device__ globals (no allocation allowed)
__device__ float g_hA[MAXN * HDIM];
__device__ float g_hB[MAXN * HDIM];
__device__ float g_pA[MAXN * HDIM];
__device__ float g_pB[MAXN * HDIM];
__device__ float g_EsA[MAXN * HDIM];
__device__ float g_EsB[MAXN * HDIM];
__device__ float g_S[MAXN * HDIM];     // "send-part" buffer (S / T1 / P1)
__device__ float g_AG[MAXN * HDIM];    // aggregate assembly buffer
__device__ float g_eraw[MAXN * 16];    // segment_sum of raw edge features
__device__ float g_deg[MAXN];          // in-degree (float)

// ---------------------------------------------------------------------------
// zero
__global__ void zero_f(float* p, int n) {
    int i = blockIdx.x * blockDim.x + threadIdx.x;
    if (i < n) p[i] = 0.0f;
}

// degree histogram (float counts are exact up to 2^24)
__global__ void deg_hist(const int* __restrict__ rec, float* __restrict__ deg, int E) {
    int i = blockIdx.x * blockDim.x + threadIdx.x;
    if (i < E) atomicAdd(&deg[rec[i]], 1.0f);
}

// segment-sum raw edge features [E,16] -> [N,16]
__global__ void e_scatter(const float* __restrict__ e, const int* __restrict__ rec,
                          float* __restrict__ out, int E) {
    int i = blockIdx.x * blockDim.x + threadIdx.x;   // over E*4, 4 floats each
    if (i < E * 4) {
        int edge = i >> 2;
        int f4 = (i & 3) * 4;
        int r = rec[edge];
        float4 v = *(const float4*)(e + (size_t)edge * 16 + f4);
        float* d = out + (size_t)r * 16 + f4;
        atomicAdd(d + 0, v.x);
        atomicAdd(d + 1, v.y);
        atomicAdd(d + 2, v.z);
        atomicAdd(d + 3, v.w);
    }
}

// dst[rec[e], :] += src[send[e], :]   (64 floats per edge, one warp per edge)
__global__ void scatter64(const float* __restrict__ src, float* __restrict__ dst,
                          const int* __restrict__ send, const int* __restrict__ rec, int E) {
    int g = blockIdx.x * blockDim.x + threadIdx.x;
    int e = g >> 5;
    if (e >= E) return;
    int lane = g & 31;
    int s = send[e];
    int r = rec[e];
    float2 v = *(const float2*)(src + (size_t)s * HDIM + lane * 2);
    float* d = dst + (size_t)r * HDIM + lane * 2;
    atomicAdd(d + 0, v.x);
    atomicAdd(d + 1, v.y);
}

// ---------------------------------------------------------------------------
// Fused row-wise GEMM:
//   C[row, :64] = degsel * ( A[row]@Wa + B[row]@Wb + bias1 ) + D[row]@Wd
// where degsel = degf[row] if degf != null else 1 (deg scaling applies to the
// A/B/bias1 part only). Any of A, B, bias1, degf, D may be null.
// All W are [K,64] row-major; K multiples of 4.
__global__ __launch_bounds__(256) void gemm_fused(
    const float* __restrict__ A, const float* __restrict__ Wa, int Ka,
    const float* __restrict__ B, const float* __restrict__ Wb, int Kb,
    const float* __restrict__ bias1, const float* __restrict__ degf,
    const float* __restrict__ D, const float* __restrict__ Wd, int Kd,
    float* __restrict__ C, int N)
{
    extern __shared__ float sw[];  // (Ka+Kb+Kd) x 64

    // cooperative weight load (each W contiguous, rows concatenated)
    {
        int nA = Ka * 64, nB = Kb * 64, nD = Kd * 64;
        for (int i = threadIdx.x * 4; i < nA; i += blockDim.x * 4)
            *(float4*)&sw[i] = *(const float4*)&Wa[i];
        for (int i = threadIdx.x * 4; i < nB; i += blockDim.x * 4)
            *(float4*)&sw[nA + i] = *(const float4*)&Wb[i];
        for (int i = threadIdx.x * 4; i < nD; i += blockDim.x * 4)
            *(float4*)&sw[nA + nB + i] = *(const float4*)&Wd[i];
    }
    __syncthreads();

    const int cg = threadIdx.x & 3;        // column group: 16 cols
    const int rl = threadIdx.x >> 2;       // 0..63
    const int row0 = blockIdx.x * 256 + rl * 4;

    float acc[4][16];
#pragma unroll
    for (int r = 0; r < 4; r++)
#pragma unroll
        for (int j = 0; j < 16; j++) acc[r][j] = 0.0f;

    int rowc[4];
#pragma unroll
    for (int r = 0; r < 4; r++) {
        int rr = row0 + r;
        rowc[r] = rr < N ? rr : (N - 1);   // clamp for safe loads; store guarded
    }

    // ---- part 1: A and B ----
#pragma unroll 1
    for (int m = 0; m < 2; m++) {
        const float* X = (m == 0) ? A : B;
        int K = (m == 0) ? Ka : Kb;
        int off = (m == 0) ? 0 : Ka;
        if (X == nullptr || K == 0) continue;
#pragma unroll 1
        for (int k4 = 0; k4 < K; k4 += 4) {
            float4 xv[4];
#pragma unroll
            for (int r = 0; r < 4; r++)
                xv[r] = *(const float4*)(X + (size_t)rowc[r] * K + k4);
#pragma unroll
            for (int kk = 0; kk < 4; kk++) {
                const float4* wrow = (const float4*)&sw[(off + k4 + kk) * 64 + cg * 16];
                float4 w0 = wrow[0], w1 = wrow[1], w2 = wrow[2], w3 = wrow[3];
#pragma unroll
                for (int r = 0; r < 4; r++) {
                    float x = (kk == 0) ? xv[r].x : (kk == 1) ? xv[r].y
                              : (kk == 2) ? xv[r].z : xv[r].w;
                    acc[r][0]  = fmaf(x, w0.x, acc[r][0]);
                    acc[r][1]  = fmaf(x, w0.y, acc[r][1]);
                    acc[r][2]  = fmaf(x, w0.z, acc[r][2]);
                    acc[r][3]  = fmaf(x, w0.w, acc[r][3]);
                    acc[r][4]  = fmaf(x, w1.x, acc[r][4]);
                    acc[r][5]  = fmaf(x, w1.y, acc[r][5]);
                    acc[r][6]  = fmaf(x, w1.z, acc[r][6]);
                    acc[r][7]  = fmaf(x, w1.w, acc[r][7]);
                    acc[r][8]  = fmaf(x, w2.x, acc[r][8]);
                    acc[r][9]  = fmaf(x, w2.y, acc[r][9]);
                    acc[r][10] = fmaf(x, w2.z, acc[r][10]);
                    acc[r][11] = fmaf(x, w2.w, acc[r][11]);
                    acc[r][12] = fmaf(x, w3.x, acc[r][12]);
                    acc[r][13] = fmaf(x, w3.y, acc[r][13]);
                    acc[r][14] = fmaf(x, w3.z, acc[r][14]);
                    acc[r][15] = fmaf(x, w3.w, acc[r][15]);
                }
            }
        }
    }

    // bias1 then deg scaling (applies only to A/B/bias1 part)
    if (bias1) {
        float4 b0 = *(const float4*)&bias1[cg * 16 + 0];
        float4 b1 = *(const float4*)&bias1[cg * 16 + 4];
        float4 b2 = *(const float4*)&bias1[cg * 16 + 8];
        float4 b3 = *(const float4*)&bias1[cg * 16 + 12];
        float bb[16] = {b0.x,b0.y,b0.z,b0.w,b1.x,b1.y,b1.z,b1.w,
                        b2.x,b2.y,b2.z,b2.w,b3.x,b3.y,b3.z,b3.w};
#pragma unroll
        for (int r = 0; r < 4; r++)
#pragma unroll
            for (int j = 0; j < 16; j++) acc[r][j] += bb[j];
    }
    if (degf) {
#pragma unroll
        for (int r = 0; r < 4; r++) {
            float dg = degf[rowc[r]];
#pragma unroll
            for (int j = 0; j < 16; j++) acc[r][j] *= dg;
        }
    }

    // ---- part 2: D (unscaled) ----
    if (D != nullptr && Kd > 0) {
        int off = Ka + Kb;
#pragma unroll 1
        for (int k4 = 0; k4 < Kd; k4 += 4) {
            float4 xv[4];
#pragma unroll
            for (int r = 0; r < 4; r++)
                xv[r] = *(const float4*)(D + (size_t)rowc[r] * Kd + k4);
#pragma unroll
            for (int kk = 0; kk < 4; kk++) {
                const float4* wrow = (const float4*)&sw[(off + k4 + kk) * 64 + cg * 16];
                float4 w0 = wrow[0], w1 = wrow[1], w2 = wrow[2], w3 = wrow[3];
#pragma unroll
                for (int r = 0; r < 4; r++) {
                    float x = (kk == 0) ? xv[r].x : (kk == 1) ? xv[r].y
                              : (kk == 2) ? xv[r].z : xv[r].w;
                    acc[r][0]  = fmaf(x, w0.x, acc[r][0]);
                    acc[r][1]  = fmaf(x, w0.y, acc[r][1]);
                    acc[r][2]  = fmaf(x, w0.z, acc[r][2]);
                    acc[r][3]  = fmaf(x, w0.w, acc[r][3]);
                    acc[r][4]  = fmaf(x, w1.x, acc[r][4]);
                    acc[r][5]  = fmaf(x, w1.y, acc[r][5]);
                    acc[r][6]  = fmaf(x, w1.z, acc[r][6]);
                    acc[r][7]  = fmaf(x, w1.w, acc[r][7]);
                    acc[r][8]  = fmaf(x, w2.x, acc[r][8]);
                    acc[r][9]  = fmaf(x, w2.y, acc[r][9]);
                    acc[r][10] = fmaf(x, w2.z, acc[r][10]);
                    acc[r][11] = fmaf(x, w2.w, acc[r][11]);
                    acc[r][12] = fmaf(x, w3.x, acc[r][12]);
                    acc[r][13] = fmaf(x, w3.y, acc[r][13]);
                    acc[r][14] = fmaf(x, w3.z, acc[r][14]);
                    acc[r][15] = fmaf(x, w3.w, acc[r][15]);
                }
            }
        }
    }

    // store
#pragma unroll
    for (int r = 0; r < 4; r++) {
        int row = row0 + r;
        if (row < N) {
            float* cp = C + (size_t)row * 64 + cg * 16;
            *(float4*)(cp + 0)  = make_float4(acc[r][0],  acc[r][1],  acc[r][2],  acc[r][3]);
            *(float4*)(cp + 4)  = make_float4(acc[r][4],  acc[r][5],  acc[r][6],  acc[r][7]);
            *(float4*)(cp + 8)  = make_float4(acc[r][8],  acc[r][9],  acc[r][10], acc[r][11]);
            *(float4*)(cp + 12) = make_float4(acc[r][12], acc[r][13], acc[r][14], acc[r][15]);
        }
    }
}

// ---------------------------------------------------------------------------
extern "C" void kernel_launch(void* const* d_in, const int* in_sizes, int n_in,
                              void* d_out, int out_size) {
    const float* h_in = (const float*)d_in[0];
    const float* e_in = (const float*)d_in[1];
    const float* p_in = (const float*)d_in[2];
    const int*   eidx = (const int*)d_in[3];
    const float* he_W = (const float*)d_in[4];
    const float* he_b = (const float*)d_in[5];
    const float* ee_W = (const float*)d_in[6];
    const float* ee_b = (const float*)d_in[7];
    const float* pe_W = (const float*)d_in[8];
    const float* pe_b = (const float*)d_in[9];
    const float* hm_W = (const float*)d_in[10];
    const float* hm_b = (const float*)d_in[11];
    const float* hu_W = (const float*)d_in[12];
    const float* hu_b = (const float*)d_in[13];
    const float* eu_W = (const float*)d_in[14];
    const float* eu_b = (const float*)d_in[15];
    const float* pm_W = (const float*)d_in[16];
    const float* pm_b = (const float*)d_in[17];
    const float* pu_W = (const float*)d_in[18];
    const float* pu_b = (const float*)d_in[19];

    const int N = in_sizes[0] / 128;      // 50000
    const int E = in_sizes[3] / 2;        // 800000
    const int* send = eidx;
    const int* rec  = eidx + E;
    float* out = (float*)d_out;

    float *hA, *hB, *pA, *pB, *EsA, *EsB, *S, *AG, *eraw, *deg;
    cudaGetSymbolAddress((void**)&hA,  g_hA);
    cudaGetSymbolAddress((void**)&hB,  g_hB);
    cudaGetSymbolAddress((void**)&pA,  g_pA);
    cudaGetSymbolAddress((void**)&pB,  g_pB);
    cudaGetSymbolAddress((void**)&EsA, g_EsA);
    cudaGetSymbolAddress((void**)&EsB, g_EsB);
    cudaGetSymbolAddress((void**)&S,   g_S);
    cudaGetSymbolAddress((void**)&AG,  g_AG);
    cudaGetSymbolAddress((void**)&eraw, g_eraw);
    cudaGetSymbolAddress((void**)&deg, g_deg);

    const int GB = (N + 255) / 256;   // gemm grid
    const int TB = 256;

    // init: deg + raw edge-feature segment sum
    zero_f<<<(N + 255) / 256, 256>>>(deg, N);
    zero_f<<<(N * 16 + 255) / 256, 256>>>(eraw, N * 16);
    deg_hist<<<(E + 255) / 256, 256>>>(rec, deg, E);
    e_scatter<<<(E * 4 + 255) / 256, 256>>>(e_in, rec, eraw, E);

    // embeddings
    gemm_fused<<<GB, TB, 128 * 64 * 4>>>(h_in, he_W, 128, nullptr, nullptr, 0,
                                         he_b, nullptr, nullptr, nullptr, 0, hA, N);
    gemm_fused<<<GB, TB, 16 * 64 * 4>>>(p_in, pe_W, 16, nullptr, nullptr, 0,
                                        pe_b, nullptr, nullptr, nullptr, 0, pA, N);
    // Esum0 = deg*ee_b + eraw@ee_W
    gemm_fused<<<GB, TB, 16 * 64 * 4>>>(nullptr, nullptr, 0, nullptr, nullptr, 0,
                                        ee_b, deg, eraw, ee_W, 16, EsA, N);

    const int SCG = (E * 32 + 255) / 256;  // scatter grid: warp per edge

    for (int l = 0; l < 4; l++) {
        const float* W1  = hm_W + (size_t)l * 320 * 64;
        const float* W2  = W1 + 64 * 64;
        const float* W3  = W1 + 128 * 64;
        const float* W4  = W1 + 192 * 64;
        const float* W5  = W1 + 256 * 64;
        const float* bhm = hm_b + (size_t)l * 64;
        const float* HuA = hu_W + (size_t)l * 128 * 64;
        const float* HuB = HuA + 64 * 64;
        const float* bhu = hu_b + (size_t)l * 64;
        const float* U1  = eu_W + (size_t)l * 192 * 64;
        const float* U2  = U1 + 64 * 64;
        const float* U3  = U1 + 128 * 64;
        const float* beu = eu_b + (size_t)l * 64;
        const float* V1  = pm_W + (size_t)l * 192 * 64;
        const float* V2  = V1 + 64 * 64;
        const float* V3  = V1 + 128 * 64;
        const float* bpm = pm_b + (size_t)l * 64;
        const float* PuA = pu_W + (size_t)l * 128 * 64;
        const float* PuB = PuA + 64 * 64;
        const float* bpu = pu_b + (size_t)l * 64;

        const bool last = (l == 3);
        float* hOut = last ? out : hB;
        float* pOut = last ? (out + (size_t)N * 64) : pB;

        // S = h@W1 + p@W2
        gemm_fused<<<GB, TB, 128 * 64 * 4>>>(hA, W1, 64, pA, W2, 64,
                                             nullptr, nullptr, nullptr, nullptr, 0, S, N);
        // AG = deg*(h@W3 + p@W4 + bhm) + Esum@W5
        gemm_fused<<<GB, TB, 192 * 64 * 4>>>(hA, W3, 64, pA, W4, 64,
                                             bhm, deg, EsA, W5, 64, AG, N);
        // AG += scatter S
        scatter64<<<SCG, 256>>>(S, AG, send, rec, E);
        // h' = h@HuA + AG@HuB + bhu
        gemm_fused<<<GB, TB, 128 * 64 * 4>>>(hA, HuA, 64, AG, HuB, 64,
                                             bhu, nullptr, nullptr, nullptr, 0, hOut, N);
        // T1 = h'@U1
        gemm_fused<<<GB, TB, 64 * 64 * 4>>>(hOut, U1, 64, nullptr, nullptr, 0,
                                            nullptr, nullptr, nullptr, nullptr, 0, S, N);
        // Esum' = deg*(h'@U2 + beu) + Esum@U3
        gemm_fused<<<GB, TB, 128 * 64 * 4>>>(hOut, U2, 64, nullptr, nullptr, 0,
                                             beu, deg, EsA, U3, 64, EsB, N);
        // Esum' += scatter T1
        scatter64<<<SCG, 256>>>(S, EsB, send, rec, E);
        // P1 = p@V1
        gemm_fused<<<GB, TB, 64 * 64 * 4>>>(pA, V1, 64, nullptr, nullptr, 0,
                                            nullptr, nullptr, nullptr, nullptr, 0, S, N);
        // AG = deg*(p@V2 + bpm) + Esum'@V3
        gemm_fused<<<GB, TB, 128 * 64 * 4>>>(pA, V2, 64, nullptr, nullptr, 0,
                                             bpm, deg, EsB, V3, 64, AG, N);
        // AG += scatter P1
        scatter64<<<SCG, 256>>>(S, AG, send, rec, E);
        // p' = p@PuA + AG@PuB + bpu
        gemm_fused<<<GB, TB, 128 * 64 * 4>>>(pA, PuA, 64, AG, PuB, 64,
                                             bpu, nullptr, nullptr, nullptr, 0, pOut, N);

        // rotate buffers
        float* t;
        t = hA; hA = hOut; hB = t;
        t = pA; pA = pOut; pB = t;
        t = EsA; EsA = EsB; EsB = t;
    }
}